// round 1
// baseline (speedup 1.0000x reference)
#include <cuda_runtime.h>
#include <cstdint>

#define MDIM 4096
#define NDIM 4096
#define KDIM 4096

// ---------------- device scratch (no allocations allowed) ----------------
__device__ unsigned g_amax[2];                              // float bits, abs-max of lhs/rhs
__device__ __align__(16) signed char g_qa[(size_t)MDIM * KDIM];      // quantized lhs, row-major
__device__ __align__(16) int         g_qbp[(size_t)(KDIM / 4) * NDIM]; // quantized rhs, K-packed: [k/4][n]

// ---------------- kernels ----------------
__global__ void init_kernel() {
    g_amax[0] = 0u;
    g_amax[1] = 0u;
}

__global__ void amax_kernel(const float* __restrict__ x, int n4, int which) {
    float m = 0.0f;
    int stride = gridDim.x * blockDim.x;
    for (int i = blockIdx.x * blockDim.x + threadIdx.x; i < n4; i += stride) {
        float4 v = reinterpret_cast<const float4*>(x)[i];
        m = fmaxf(m, fmaxf(fmaxf(fabsf(v.x), fabsf(v.y)), fmaxf(fabsf(v.z), fabsf(v.w))));
    }
#pragma unroll
    for (int o = 16; o > 0; o >>= 1)
        m = fmaxf(m, __shfl_xor_sync(0xFFFFFFFFu, m, o));
    if ((threadIdx.x & 31) == 0)
        atomicMax(&g_amax[which], __float_as_uint(m));   // m >= 0 -> uint order == float order
}

__device__ __forceinline__ float get_scale(int which) {
    float amax = __uint_as_float(g_amax[which]);
    return 127.0f / fmaxf(amax, 1e-12f);
}

__device__ __forceinline__ int q8(float x, float s) {
    float r = rintf(x * s);                      // round-half-to-even, matches jnp.round
    r = fmaxf(-127.0f, fminf(127.0f, r));
    return (int)r;
}

// lhs -> row-major int8
__global__ void quant_a_kernel(const float* __restrict__ lhs) {
    int idx = blockIdx.x * blockDim.x + threadIdx.x;   // 4M threads, 4 elems each
    float s = get_scale(0);
    float4 v = reinterpret_cast<const float4*>(lhs)[idx];
    char4 q;
    q.x = (signed char)q8(v.x, s);
    q.y = (signed char)q8(v.y, s);
    q.z = (signed char)q8(v.z, s);
    q.w = (signed char)q8(v.w, s);
    reinterpret_cast<char4*>(g_qa)[idx] = q;
}

// rhs -> K-packed int8: g_qbp[kg * NDIM + n] packs rhs[4kg+0..3][n] in bytes 0..3
__global__ void quant_b_kernel(const float* __restrict__ rhs) {
    int id = blockIdx.x * blockDim.x + threadIdx.x;    // (K/4)*N threads
    int kg = id >> 12;           // / NDIM
    int n  = id & (NDIM - 1);
    float s = get_scale(1);
    const float* p = rhs + (size_t)(kg * 4) * NDIM + n;
    int b0 = q8(p[0 * NDIM], s) & 0xFF;
    int b1 = q8(p[1 * NDIM], s) & 0xFF;
    int b2 = q8(p[2 * NDIM], s) & 0xFF;
    int b3 = q8(p[3 * NDIM], s) & 0xFF;
    g_qbp[id] = b0 | (b1 << 8) | (b2 << 16) | (b3 << 24);
}

// ---------------- int8 GEMM: 128x128 block tile, K-chunk 64, mma.m16n8k32 ----------------
__global__ void __launch_bounds__(256) gemm_s8_kernel(float* __restrict__ out) {
    __shared__ signed char As[128][80];   // padded: conflict-free fragment loads
    __shared__ int         Bs[16][132];   // K-packed rows, padded

    const int tid  = threadIdx.x;
    const int lane = tid & 31;
    const int warp = tid >> 5;
    const int wm = warp & 3;              // 4 warps along M
    const int wn = warp >> 2;             // 2 warps along N
    const int g = lane >> 2;              // groupID
    const int t = lane & 3;               // threadID in group

    const int mBase = blockIdx.y * 128;
    const int nBase = blockIdx.x * 128;

    int c[2][8][4];
#pragma unroll
    for (int mi = 0; mi < 2; mi++)
#pragma unroll
        for (int ni = 0; ni < 8; ni++)
#pragma unroll
            for (int r = 0; r < 4; r++) c[mi][ni][r] = 0;

    for (int kt = 0; kt < KDIM; kt += 64) {
        // load A tile: 128 rows x 64 bytes = 512 int4
#pragma unroll
        for (int it = 0; it < 2; it++) {
            int i = tid + it * 256;
            int row = i >> 2, seg = i & 3;
            const int4* src = reinterpret_cast<const int4*>(
                g_qa + (size_t)(mBase + row) * KDIM + kt + seg * 16);
            *reinterpret_cast<int4*>(&As[row][seg * 16]) = *src;
        }
        // load B tile: 16 packed rows x 128 ints = 512 int4
#pragma unroll
        for (int it = 0; it < 2; it++) {
            int i = tid + it * 256;
            int row = i >> 5, seg = i & 31;
            const int4* src = reinterpret_cast<const int4*>(
                g_qbp + (size_t)((kt >> 2) + row) * NDIM + nBase + seg * 4);
            *reinterpret_cast<int4*>(&Bs[row][seg * 4]) = *src;
        }
        __syncthreads();

#pragma unroll
        for (int ks = 0; ks < 64; ks += 32) {
            int a[2][4];
#pragma unroll
            for (int mi = 0; mi < 2; mi++) {
                int row = wm * 32 + mi * 16 + g;
                a[mi][0] = *reinterpret_cast<const int*>(&As[row][ks + t * 4]);
                a[mi][1] = *reinterpret_cast<const int*>(&As[row + 8][ks + t * 4]);
                a[mi][2] = *reinterpret_cast<const int*>(&As[row][ks + 16 + t * 4]);
                a[mi][3] = *reinterpret_cast<const int*>(&As[row + 8][ks + 16 + t * 4]);
            }
#pragma unroll
            for (int ni = 0; ni < 8; ni++) {
                int col = wn * 64 + ni * 8 + g;
                int b0 = Bs[(ks >> 2) + t][col];
                int b1 = Bs[(ks >> 2) + 4 + t][col];
#pragma unroll
                for (int mi = 0; mi < 2; mi++) {
                    asm volatile(
                        "mma.sync.aligned.m16n8k32.row.col.s32.s8.s8.s32 "
                        "{%0,%1,%2,%3}, {%4,%5,%6,%7}, {%8,%9}, {%0,%1,%2,%3};\n"
                        : "+r"(c[mi][ni][0]), "+r"(c[mi][ni][1]),
                          "+r"(c[mi][ni][2]), "+r"(c[mi][ni][3])
                        : "r"(a[mi][0]), "r"(a[mi][1]), "r"(a[mi][2]), "r"(a[mi][3]),
                          "r"(b0), "r"(b1));
                }
            }
        }
        __syncthreads();
    }

    // epilogue: dequant by exact fp32 division (matches reference semantics)
    float ls = get_scale(0);
    float rs = get_scale(1);
    float d = ls * rs;

#pragma unroll
    for (int mi = 0; mi < 2; mi++) {
#pragma unroll
        for (int ni = 0; ni < 8; ni++) {
            int row0 = mBase + wm * 32 + mi * 16 + g;
            int col  = nBase + wn * 64 + ni * 8 + t * 2;
            float2 v0, v1;
            v0.x = (float)c[mi][ni][0] / d;
            v0.y = (float)c[mi][ni][1] / d;
            v1.x = (float)c[mi][ni][2] / d;
            v1.y = (float)c[mi][ni][3] / d;
            *reinterpret_cast<float2*>(out + (size_t)row0 * NDIM + col) = v0;
            *reinterpret_cast<float2*>(out + (size_t)(row0 + 8) * NDIM + col) = v1;
        }
    }
}

// ---------------- launch ----------------
extern "C" void kernel_launch(void* const* d_in, const int* in_sizes, int n_in,
                              void* d_out, int out_size) {
    const float* lhs = (const float*)d_in[0];
    const float* rhs = (const float*)d_in[1];
    float* out = (float*)d_out;

    init_kernel<<<1, 1>>>();
    amax_kernel<<<2048, 256>>>(lhs, (MDIM * KDIM) / 4, 0);
    amax_kernel<<<2048, 256>>>(rhs, (KDIM * NDIM) / 4, 1);
    quant_a_kernel<<<(MDIM * KDIM / 4) / 256, 256>>>(lhs);
    quant_b_kernel<<<((KDIM / 4) * NDIM) / 256, 256>>>(rhs);
    dim3 grid(NDIM / 128, MDIM / 128);
    gemm_s8_kernel<<<grid, 256>>>(out);
}

// round 3
// speedup vs baseline: 1.0152x; 1.0152x over previous
#include <cuda_runtime.h>
#include <cstdint>

#define MDIM 4096
#define NDIM 4096
#define KDIM 4096

// ---------------- device scratch (no allocations allowed) ----------------
__device__ unsigned g_amax[2];                                    // float bits
__device__ __align__(128) signed char g_qa[(size_t)MDIM * KDIM];  // lhs int8, [M][K]
__device__ __align__(128) int g_qbp[(size_t)(KDIM / 4) * NDIM];   // rhs int8 K-packed: [k/4][n]

// ---------------- calibration ----------------
__global__ void init_kernel() { g_amax[0] = 0u; g_amax[1] = 0u; }

__global__ void amax_kernel(const float* __restrict__ x, int n4, int which) {
    float m = 0.0f;
    int stride = gridDim.x * blockDim.x;
    for (int i = blockIdx.x * blockDim.x + threadIdx.x; i < n4; i += stride) {
        float4 v = reinterpret_cast<const float4*>(x)[i];
        m = fmaxf(m, fmaxf(fmaxf(fabsf(v.x), fabsf(v.y)), fmaxf(fabsf(v.z), fabsf(v.w))));
    }
#pragma unroll
    for (int o = 16; o > 0; o >>= 1)
        m = fmaxf(m, __shfl_xor_sync(0xFFFFFFFFu, m, o));
    if ((threadIdx.x & 31) == 0)
        atomicMax(&g_amax[which], __float_as_uint(m));  // m >= 0: uint order == float order
}

__device__ __forceinline__ float get_scale(int which) {
    float amax = __uint_as_float(g_amax[which]);
    return 127.0f / fmaxf(amax, 1e-12f);
}

__device__ __forceinline__ int q8(float x, float s) {
    float r = rintf(x * s);  // round-half-even, matches jnp.round
    r = fmaxf(-127.0f, fminf(127.0f, r));
    return (int)r;
}

// lhs -> row-major int8 [M][K]
__global__ void quant_a_kernel(const float* __restrict__ lhs) {
    int idx = blockIdx.x * blockDim.x + threadIdx.x;
    float s = get_scale(0);
    float4 v = reinterpret_cast<const float4*>(lhs)[idx];
    char4 q;
    q.x = (signed char)q8(v.x, s);
    q.y = (signed char)q8(v.y, s);
    q.z = (signed char)q8(v.z, s);
    q.w = (signed char)q8(v.w, s);
    reinterpret_cast<char4*>(g_qa)[idx] = q;
}

// rhs -> K-packed int8: g_qbp[kg * NDIM + n] packs rhs[4kg+0..3][n] in bytes 0..3
__global__ void quant_b_kernel(const float* __restrict__ rhs) {
    int id = blockIdx.x * blockDim.x + threadIdx.x;  // (K/4)*N threads
    int kg = id >> 12;        // / NDIM
    int n = id & (NDIM - 1);
    float s = get_scale(1);
    const float* p = rhs + (size_t)(kg * 4) * NDIM + n;
    int b0 = q8(p[0 * NDIM], s) & 0xFF;
    int b1 = q8(p[1 * NDIM], s) & 0xFF;
    int b2 = q8(p[2 * NDIM], s) & 0xFF;
    int b3 = q8(p[3 * NDIM], s) & 0xFF;
    g_qbp[id] = b0 | (b1 << 8) | (b2 << 16) | (b3 << 24);
}

// ---------------- pipelined int8 GEMM ----------------
// 128x128 CTA tile, K-chunk 64, 4-stage cp.async ring, 8 warps (4x2), warp tile 32x64.
// Stage layout (dynamic smem): A 128 rows x 80B stride (64B payload), then B 16 packed
// rows x 136 ints stride (128 ints payload).
#define NS 4
#define AST 80                    // A row stride, bytes
#define BSTI 136                  // B row stride, ints (conflict-free: bank step 8)
#define A_BYTES (128 * AST)       // 10240
#define B_BYTES (16 * BSTI * 4)   // 8704
#define STAGE (A_BYTES + B_BYTES) // 18944 (128-aligned)
#define GEMM_SMEM (NS * STAGE)    // 75776
#define NC (KDIM / 64)            // 64 chunks

__device__ __forceinline__ uint32_t smem_u32(const void* p) {
    uint32_t a;
    asm("{ .reg .u64 t; cvta.to.shared.u64 t, %1; cvt.u32.u64 %0, t; }" : "=r"(a) : "l"(p));
    return a;
}

__global__ void __launch_bounds__(256, 2) gemm_s8_kernel(float* __restrict__ out) {
    extern __shared__ char sm[];
    const uint32_t sb = smem_u32(sm);

    const int tid = threadIdx.x;
    const int lane = tid & 31;
    const int warp = tid >> 5;
    const int wm = warp & 3;   // 4 warps along M
    const int wn = warp >> 2;  // 2 warps along N
    const int g = lane >> 2;   // groupID
    const int t = lane & 3;    // threadID in group

    const int mBase = blockIdx.y * 128;
    const int nBase = blockIdx.x * 128;

    int acc[2][8][4];
#pragma unroll
    for (int mi = 0; mi < 2; mi++)
#pragma unroll
        for (int ni = 0; ni < 8; ni++)
#pragma unroll
            for (int r = 0; r < 4; r++) acc[mi][ni][r] = 0;

    // precomputed per-thread load offsets
    const int a_row0 = tid >> 2, a_seg0 = tid & 3;
    const int b_row0 = tid >> 5, b_seg0 = tid & 31;

    // ---- issue loads for chunk ch into stage ch&3 (all 256 threads) ----
    auto issue = [&](int ch) {
        if (ch < NC) {
            const int kt = ch * 64;
            const uint32_t st = sb + (ch & 3) * STAGE;
#pragma unroll
            for (int it = 0; it < 2; it++) {
                int row = a_row0 + it * 64;
                uint32_t dst = st + row * AST + a_seg0 * 16;
                const void* src = g_qa + (size_t)(mBase + row) * KDIM + kt + a_seg0 * 16;
                asm volatile("cp.async.cg.shared.global [%0], [%1], 16;"
                             :: "r"(dst), "l"(src) : "memory");
            }
#pragma unroll
            for (int it = 0; it < 2; it++) {
                int row = b_row0 + it * 8;
                uint32_t dst = st + A_BYTES + row * (BSTI * 4) + b_seg0 * 16;
                const void* src = g_qbp + (size_t)((kt >> 2) + row) * NDIM + nBase + b_seg0 * 4;
                asm volatile("cp.async.cg.shared.global [%0], [%1], 16;"
                             :: "r"(dst), "l"(src) : "memory");
            }
        }
        asm volatile("cp.async.commit_group;" ::: "memory");
    };

    // prologue: stages 0..2 in flight
    issue(0);
    issue(1);
    issue(2);

    for (int ch = 0; ch < NC; ch++) {
        asm volatile("cp.async.wait_group 2;" ::: "memory");  // chunk ch complete
        __syncthreads();                                      // visible to all threads
        issue(ch + 3);                                        // overlap next loads with MMA

        const char* As = sm + (ch & 3) * STAGE;
        const int* Bs = reinterpret_cast<const int*>(As + A_BYTES);

#pragma unroll
        for (int ks = 0; ks < 64; ks += 32) {
            int a[2][4];
#pragma unroll
            for (int mi = 0; mi < 2; mi++) {
                int row = wm * 32 + mi * 16 + g;
                a[mi][0] = *reinterpret_cast<const int*>(&As[row * AST + ks + t * 4]);
                a[mi][1] = *reinterpret_cast<const int*>(&As[(row + 8) * AST + ks + t * 4]);
                a[mi][2] = *reinterpret_cast<const int*>(&As[row * AST + ks + 16 + t * 4]);
                a[mi][3] = *reinterpret_cast<const int*>(&As[(row + 8) * AST + ks + 16 + t * 4]);
            }
#pragma unroll
            for (int ni = 0; ni < 8; ni++) {
                int col = wn * 64 + ni * 8 + g;
                int b0 = Bs[((ks >> 2) + t) * BSTI + col];
                int b1 = Bs[((ks >> 2) + 4 + t) * BSTI + col];
#pragma unroll
                for (int mi = 0; mi < 2; mi++) {
                    asm volatile(
                        "mma.sync.aligned.m16n8k32.row.col.s32.s8.s8.s32 "
                        "{%0,%1,%2,%3}, {%4,%5,%6,%7}, {%8,%9}, {%0,%1,%2,%3};\n"
                        : "+r"(acc[mi][ni][0]), "+r"(acc[mi][ni][1]),
                          "+r"(acc[mi][ni][2]), "+r"(acc[mi][ni][3])
                        : "r"(a[mi][0]), "r"(a[mi][1]), "r"(a[mi][2]), "r"(a[mi][3]),
                          "r"(b0), "r"(b1));
                }
            }
        }
    }

    // ---------------- epilogue: exact fp32 dequant ----------------
    float d = get_scale(0) * get_scale(1);
    float inv = 1.0f / d;

#pragma unroll
    for (int mi = 0; mi < 2; mi++) {
#pragma unroll
        for (int ni = 0; ni < 8; ni++) {
            int row0 = mBase + wm * 32 + mi * 16 + g;
            int col = nBase + wn * 64 + ni * 8 + t * 2;
            float2 v0, v1;
            v0.x = (float)acc[mi][ni][0] * inv;
            v0.y = (float)acc[mi][ni][1] * inv;
            v1.x = (float)acc[mi][ni][2] * inv;
            v1.y = (float)acc[mi][ni][3] * inv;
            *reinterpret_cast<float2*>(out + (size_t)row0 * NDIM + col) = v0;
            *reinterpret_cast<float2*>(out + (size_t)(row0 + 8) * NDIM + col) = v1;
        }
    }
}

// ---------------- launch ----------------
extern "C" void kernel_launch(void* const* d_in, const int* in_sizes, int n_in,
                              void* d_out, int out_size) {
    const float* lhs = (const float*)d_in[0];
    const float* rhs = (const float*)d_in[1];
    float* out = (float*)d_out;

    cudaFuncSetAttribute(gemm_s8_kernel,
                         cudaFuncAttributeMaxDynamicSharedMemorySize, GEMM_SMEM);

    init_kernel<<<1, 1>>>();
    amax_kernel<<<2048, 256>>>(lhs, (MDIM * KDIM) / 4, 0);
    amax_kernel<<<2048, 256>>>(rhs, (KDIM * NDIM) / 4, 1);
    quant_a_kernel<<<(MDIM * KDIM / 4) / 256, 256>>>(lhs);
    quant_b_kernel<<<((KDIM / 4) * NDIM) / 256, 256>>>(rhs);

    dim3 grid(NDIM / 128, MDIM / 128);
    gemm_s8_kernel<<<grid, 256, GEMM_SMEM>>>(out);
}

// round 5
// speedup vs baseline: 2.2599x; 2.2260x over previous
#include <cuda_runtime.h>
#include <cuda_bf16.h>
#include <cstdint>

#define MDIM 4096
#define NDIM 4096
#define KDIM 4096

// ---------------- device scratch (no allocations allowed) ----------------
__device__ unsigned g_amax[2];                                        // float bits
__device__ __align__(128) unsigned short g_qa[(size_t)MDIM * KDIM];   // lhs quantized ints as bf16, [M][K]
__device__ __align__(128) unsigned short g_qb[(size_t)KDIM * NDIM];   // rhs quantized ints as bf16, [K][N]

// ---------------- calibration ----------------
__global__ void init_kernel() { g_amax[0] = 0u; g_amax[1] = 0u; }

__global__ void amax_kernel(const float* __restrict__ x, int n4, int which) {
    float m = 0.0f;
    int stride = gridDim.x * blockDim.x;
    for (int i = blockIdx.x * blockDim.x + threadIdx.x; i < n4; i += stride) {
        float4 v = reinterpret_cast<const float4*>(x)[i];
        m = fmaxf(m, fmaxf(fmaxf(fabsf(v.x), fabsf(v.y)), fmaxf(fabsf(v.z), fabsf(v.w))));
    }
#pragma unroll
    for (int o = 16; o > 0; o >>= 1)
        m = fmaxf(m, __shfl_xor_sync(0xFFFFFFFFu, m, o));
    if ((threadIdx.x & 31) == 0)
        atomicMax(&g_amax[which], __float_as_uint(m));  // m >= 0: uint order == float order
}

__device__ __forceinline__ float get_scale(int which) {
    float amax = __uint_as_float(g_amax[which]);
    return 127.0f / fmaxf(amax, 1e-12f);
}

// quantize to int on the int8 grid, return EXACT bf16 representation (|v|<=127)
__device__ __forceinline__ unsigned short q8_bf16(float x, float s) {
    float r = rintf(x * s);  // round-half-even, matches jnp.round
    r = fmaxf(-127.0f, fminf(127.0f, r));
    return __bfloat16_as_ushort(__float2bfloat16_rn(r));   // ints <=127 exact in bf16
}

// elementwise quantize: float -> bf16-int. Destination resolved ON DEVICE (g_qa/g_qb
// are __device__ symbols; taking their address in host code is invalid).
__global__ void quant_kernel(const float* __restrict__ x, int which) {
    unsigned short* __restrict__ q = which ? g_qb : g_qa;
    int idx = blockIdx.x * blockDim.x + threadIdx.x;   // one float4 -> 4 bf16 (uint2)
    float s = get_scale(which);
    float4 v = reinterpret_cast<const float4*>(x)[idx];
    uint2 o;
    o.x = (uint32_t)q8_bf16(v.x, s) | ((uint32_t)q8_bf16(v.y, s) << 16);
    o.y = (uint32_t)q8_bf16(v.z, s) | ((uint32_t)q8_bf16(v.w, s) << 16);
    reinterpret_cast<uint2*>(q)[idx] = o;
}

// ---------------- bf16 HMMA GEMM ----------------
// CTA tile 128x128, K-chunk 64, 3-stage cp.async ring (32KB/stage), 8 warps (4Mx2N),
// warp tile 32x64. A smem: 128 rows x 128B (XOR-swizzled). B smem: 64 k-rows x 256B
// (XOR-swizzled). ldmatrix A (non-trans) / B (.trans), mma m16n8k16 f32.bf16.
#define NSTG 3
#define A_ST_BYTES 16384            // 128 rows * 128B
#define STAGE_BYTES 32768
#define GEMM_SMEM (NSTG * STAGE_BYTES)   // 98304
#define NC (KDIM / 64)

__device__ __forceinline__ uint32_t smem_u32(const void* p) {
    uint32_t a;
    asm("{ .reg .u64 t; cvta.to.shared.u64 t, %1; cvt.u32.u64 %0, t; }" : "=r"(a) : "l"(p));
    return a;
}

__global__ void __launch_bounds__(256, 1) gemm_bf16_kernel(float* __restrict__ out) {
    extern __shared__ char sm[];
    const uint32_t sb = smem_u32(sm);

    const int tid  = threadIdx.x;
    const int lane = tid & 31;
    const int warp = tid >> 5;
    const int wm = warp & 3;               // 4 warps along M
    const int wn = warp >> 2;              // 2 warps along N
    const int lg = lane >> 2;              // groupID
    const int lt = lane & 3;               // threadID in group

    const int mBase = blockIdx.y * 128;
    const int nBase = blockIdx.x * 128;

    float acc[2][8][4];
#pragma unroll
    for (int mi = 0; mi < 2; mi++)
#pragma unroll
        for (int ni = 0; ni < 8; ni++)
#pragma unroll
            for (int r = 0; r < 4; r++) acc[mi][ni][r] = 0.0f;

    // ---- cp.async issue for chunk ch into stage ch%3 ----
    auto issue = [&](int ch) {
        if (ch < NC) {
            const int kt = ch * 64;
            const uint32_t st = sb + (ch % NSTG) * STAGE_BYTES;
            // A: 128 rows x 128B = 1024 x 16B; 4 per thread
#pragma unroll
            for (int it = 0; it < 4; it++) {
                int c = tid + it * 256;
                int row = c >> 3, cb = c & 7;
                uint32_t dst = st + row * 128 + ((cb ^ (row & 7)) << 4);
                const void* src = g_qa + (size_t)(mBase + row) * KDIM + kt + cb * 8;
                asm volatile("cp.async.cg.shared.global [%0], [%1], 16;"
                             :: "r"(dst), "l"(src) : "memory");
            }
            // B: 64 k-rows x 256B = 1024 x 16B; 4 per thread
#pragma unroll
            for (int it = 0; it < 4; it++) {
                int c = tid + it * 256;
                int row = c >> 4, cb = c & 15;
                uint32_t dst = st + A_ST_BYTES + row * 256 + ((cb ^ (row & 7)) << 4);
                const void* src = g_qb + (size_t)(kt + row) * NDIM + nBase + cb * 8;
                asm volatile("cp.async.cg.shared.global [%0], [%1], 16;"
                             :: "r"(dst), "l"(src) : "memory");
            }
        }
        asm volatile("cp.async.commit_group;" ::: "memory");
    };

    issue(0); issue(1); issue(2);

    for (int ch = 0; ch < NC; ch++) {
        asm volatile("cp.async.wait_group 2;" ::: "memory");   // chunk ch resident
        __syncthreads();

        const uint32_t stA = sb + (ch % NSTG) * STAGE_BYTES;
        const uint32_t stB = stA + A_ST_BYTES;

#pragma unroll
        for (int ks = 0; ks < 4; ks++) {                       // 4 k-steps of 16
            // ---- A fragments: 2 x ldmatrix.x4 ----
            uint32_t a[2][4];
#pragma unroll
            for (int mi = 0; mi < 2; mi++) {
                int row = wm * 32 + mi * 16 + (lane & 15);
                int cb  = ks * 2 + (lane >> 4);
                uint32_t addr = stA + row * 128 + ((cb ^ (row & 7)) << 4);
                asm volatile("ldmatrix.sync.aligned.m8n8.x4.shared.b16 {%0,%1,%2,%3}, [%4];"
                             : "=r"(a[mi][0]), "=r"(a[mi][1]), "=r"(a[mi][2]), "=r"(a[mi][3])
                             : "r"(addr));
            }
            // ---- B fragments: 4 x ldmatrix.x4.trans, each covers 2 ni ----
            uint32_t b[4][4];
#pragma unroll
            for (int p = 0; p < 4; p++) {
                int krow = ks * 16 + (lane & 15);
                int cb   = (wn * 8 + p * 2) + (lane >> 4);     // 16B chunk along N
                uint32_t addr = stB + krow * 256 + ((cb ^ (krow & 7)) << 4);
                asm volatile("ldmatrix.sync.aligned.m8n8.x4.trans.shared.b16 {%0,%1,%2,%3}, [%4];"
                             : "=r"(b[p][0]), "=r"(b[p][1]), "=r"(b[p][2]), "=r"(b[p][3])
                             : "r"(addr));
            }
            // ---- 16 MMAs ----
#pragma unroll
            for (int p = 0; p < 4; p++) {
#pragma unroll
                for (int h = 0; h < 2; h++) {
                    int ni = p * 2 + h;
#pragma unroll
                    for (int mi = 0; mi < 2; mi++) {
                        asm volatile(
                            "mma.sync.aligned.m16n8k16.row.col.f32.bf16.bf16.f32 "
                            "{%0,%1,%2,%3}, {%4,%5,%6,%7}, {%8,%9}, {%0,%1,%2,%3};\n"
                            : "+f"(acc[mi][ni][0]), "+f"(acc[mi][ni][1]),
                              "+f"(acc[mi][ni][2]), "+f"(acc[mi][ni][3])
                            : "r"(a[mi][0]), "r"(a[mi][1]), "r"(a[mi][2]), "r"(a[mi][3]),
                              "r"(b[p][2 * h]), "r"(b[p][2 * h + 1]));
                    }
                }
            }
        }
        __syncthreads();          // all warps done with stage ch%3
        issue(ch + 3);            // refill it
    }

    // ---------------- epilogue: exact fp32 dequant ----------------
    float inv = 1.0f / (get_scale(0) * get_scale(1));

#pragma unroll
    for (int mi = 0; mi < 2; mi++) {
#pragma unroll
        for (int ni = 0; ni < 8; ni++) {
            int row0 = mBase + wm * 32 + mi * 16 + lg;
            int col  = nBase + wn * 64 + ni * 8 + lt * 2;
            float2 v0, v1;
            v0.x = acc[mi][ni][0] * inv;
            v0.y = acc[mi][ni][1] * inv;
            v1.x = acc[mi][ni][2] * inv;
            v1.y = acc[mi][ni][3] * inv;
            *reinterpret_cast<float2*>(out + (size_t)row0 * NDIM + col) = v0;
            *reinterpret_cast<float2*>(out + (size_t)(row0 + 8) * NDIM + col) = v1;
        }
    }
}

// ---------------- launch ----------------
extern "C" void kernel_launch(void* const* d_in, const int* in_sizes, int n_in,
                              void* d_out, int out_size) {
    const float* lhs = (const float*)d_in[0];
    const float* rhs = (const float*)d_in[1];
    float* out = (float*)d_out;

    cudaFuncSetAttribute(gemm_bf16_kernel,
                         cudaFuncAttributeMaxDynamicSharedMemorySize, GEMM_SMEM);

    init_kernel<<<1, 1>>>();
    amax_kernel<<<2048, 256>>>(lhs, (MDIM * KDIM) / 4, 0);
    amax_kernel<<<2048, 256>>>(rhs, (KDIM * NDIM) / 4, 1);
    quant_kernel<<<(MDIM * KDIM / 4) / 256, 256>>>(lhs, 0);
    quant_kernel<<<(KDIM * NDIM / 4) / 256, 256>>>(rhs, 1);

    dim3 grid(NDIM / 128, MDIM / 128);
    gemm_bf16_kernel<<<grid, 256, GEMM_SMEM>>>(out);
}

// round 6
// speedup vs baseline: 2.3457x; 1.0380x over previous
#include <cuda_runtime.h>
#include <cuda_bf16.h>
#include <cstdint>

#define MDIM 4096
#define NDIM 4096
#define KDIM 4096

// ---------------- device scratch (no allocations allowed) ----------------
__device__ unsigned g_amax[2];                                        // float bits
__device__ __align__(128) unsigned short g_qa[(size_t)MDIM * KDIM];   // lhs quantized ints as bf16, [M][K]
__device__ __align__(128) unsigned short g_qb[(size_t)KDIM * NDIM];   // rhs quantized ints as bf16, [K][N]

// ---------------- calibration ----------------
__global__ void init_kernel() { g_amax[0] = 0u; g_amax[1] = 0u; }

__global__ void amax_kernel(const float* __restrict__ x, int n4, int which) {
    float m = 0.0f;
    int stride = gridDim.x * blockDim.x;
    for (int i = blockIdx.x * blockDim.x + threadIdx.x; i < n4; i += stride) {
        float4 v = reinterpret_cast<const float4*>(x)[i];
        m = fmaxf(m, fmaxf(fmaxf(fabsf(v.x), fabsf(v.y)), fmaxf(fabsf(v.z), fabsf(v.w))));
    }
#pragma unroll
    for (int o = 16; o > 0; o >>= 1)
        m = fmaxf(m, __shfl_xor_sync(0xFFFFFFFFu, m, o));
    if ((threadIdx.x & 31) == 0)
        atomicMax(&g_amax[which], __float_as_uint(m));  // m >= 0: uint order == float order
}

__device__ __forceinline__ float get_scale(int which) {
    float amax = __uint_as_float(g_amax[which]);
    return 127.0f / fmaxf(amax, 1e-12f);
}

// quantize to int on the int8 grid, return EXACT bf16 representation (|v|<=127)
__device__ __forceinline__ unsigned short q8_bf16(float x, float s) {
    float r = rintf(x * s);  // round-half-even, matches jnp.round
    r = fmaxf(-127.0f, fminf(127.0f, r));
    return __bfloat16_as_ushort(__float2bfloat16_rn(r));   // ints <=127 exact in bf16
}

// elementwise quantize: 4 float4 per thread (MLP 4). Destination resolved ON DEVICE.
__global__ void quant_kernel(const float* __restrict__ x, int which) {
    unsigned short* __restrict__ q = which ? g_qb : g_qa;
    float s = get_scale(which);
    int base = (blockIdx.x * blockDim.x + threadIdx.x) * 4;
#pragma unroll
    for (int j = 0; j < 4; j++) {
        int idx = base + j;
        float4 v = reinterpret_cast<const float4*>(x)[idx];
        uint2 o;
        o.x = (uint32_t)q8_bf16(v.x, s) | ((uint32_t)q8_bf16(v.y, s) << 16);
        o.y = (uint32_t)q8_bf16(v.z, s) | ((uint32_t)q8_bf16(v.w, s) << 16);
        reinterpret_cast<uint2*>(q)[idx] = o;
    }
}

// ---------------- bf16 HMMA GEMM ----------------
// CTA tile 256x128 (MxN), K-chunk 64, 4-stage cp.async ring (48KB/stage), 8 warps
// (4Mx2N), warp tile 64x64. A smem: 256 rows x 128B (XOR-swizzled). B smem: 64 k-rows
// x 256B (XOR-swizzled). ldmatrix A / B.trans, mma m16n8k16 f32.bf16. One sync/chunk.
#define NSTG 4
#define A_ST_BYTES 32768                 // 256 rows * 128B
#define STAGE_BYTES 49152                // A 32KB + B 16KB
#define GEMM_SMEM (NSTG * STAGE_BYTES)   // 196608
#define NC (KDIM / 64)

__device__ __forceinline__ uint32_t smem_u32(const void* p) {
    uint32_t a;
    asm("{ .reg .u64 t; cvta.to.shared.u64 t, %1; cvt.u32.u64 %0, t; }" : "=r"(a) : "l"(p));
    return a;
}

__global__ void __launch_bounds__(256, 1) gemm_bf16_kernel(float* __restrict__ out) {
    extern __shared__ char sm[];
    const uint32_t sb = smem_u32(sm);

    const int tid  = threadIdx.x;
    const int lane = tid & 31;
    const int warp = tid >> 5;
    const int wm = warp & 3;               // 4 warps along M (64 rows each)
    const int wn = warp >> 2;              // 2 warps along N (64 cols each)
    const int lg = lane >> 2;              // groupID
    const int lt = lane & 3;               // threadID in group

    const int mBase = blockIdx.y * 256;
    const int nBase = blockIdx.x * 128;

    float acc[4][8][4];
#pragma unroll
    for (int mi = 0; mi < 4; mi++)
#pragma unroll
        for (int ni = 0; ni < 8; ni++)
#pragma unroll
            for (int r = 0; r < 4; r++) acc[mi][ni][r] = 0.0f;

    // ---- cp.async issue for chunk ch into stage ch%4 ----
    auto issue = [&](int ch) {
        if (ch < NC) {
            const int kt = ch * 64;
            const uint32_t st = sb + (ch % NSTG) * STAGE_BYTES;
            // A: 256 rows x 128B = 2048 x 16B; 8 per thread
#pragma unroll
            for (int it = 0; it < 8; it++) {
                int c = tid + it * 256;
                int row = c >> 3, cb = c & 7;
                uint32_t dst = st + row * 128 + ((cb ^ (row & 7)) << 4);
                const void* src = g_qa + (size_t)(mBase + row) * KDIM + kt + cb * 8;
                asm volatile("cp.async.cg.shared.global [%0], [%1], 16;"
                             :: "r"(dst), "l"(src) : "memory");
            }
            // B: 64 k-rows x 256B = 1024 x 16B; 4 per thread
#pragma unroll
            for (int it = 0; it < 4; it++) {
                int c = tid + it * 256;
                int row = c >> 4, cb = c & 15;
                uint32_t dst = st + A_ST_BYTES + row * 256 + ((cb ^ (row & 7)) << 4);
                const void* src = g_qb + (size_t)(kt + row) * NDIM + nBase + cb * 8;
                asm volatile("cp.async.cg.shared.global [%0], [%1], 16;"
                             :: "r"(dst), "l"(src) : "memory");
            }
        }
        asm volatile("cp.async.commit_group;" ::: "memory");
    };

    issue(0); issue(1); issue(2);

    for (int ch = 0; ch < NC; ch++) {
        asm volatile("cp.async.wait_group 2;" ::: "memory");   // chunk ch resident
        __syncthreads();                                       // visible; stage ch-1 free
        issue(ch + 3);                                         // refill stage (ch-1)%4

        const uint32_t stA = sb + (ch % NSTG) * STAGE_BYTES;
        const uint32_t stB = stA + A_ST_BYTES;

#pragma unroll
        for (int ks = 0; ks < 4; ks++) {                       // 4 k-steps of 16
            // ---- A fragments: 4 x ldmatrix.x4 ----
            uint32_t a[4][4];
#pragma unroll
            for (int mi = 0; mi < 4; mi++) {
                int row = wm * 64 + mi * 16 + (lane & 15);
                int cb  = ks * 2 + (lane >> 4);
                uint32_t addr = stA + row * 128 + ((cb ^ (row & 7)) << 4);
                asm volatile("ldmatrix.sync.aligned.m8n8.x4.shared.b16 {%0,%1,%2,%3}, [%4];"
                             : "=r"(a[mi][0]), "=r"(a[mi][1]), "=r"(a[mi][2]), "=r"(a[mi][3])
                             : "r"(addr));
            }
            // ---- B fragments: 4 x ldmatrix.x4.trans, each covers 2 ni ----
            uint32_t b[4][4];
#pragma unroll
            for (int p = 0; p < 4; p++) {
                int krow = ks * 16 + (lane & 15);
                int cb   = (wn * 8 + p * 2) + (lane >> 4);     // 16B chunk along N
                uint32_t addr = stB + krow * 256 + ((cb ^ (krow & 7)) << 4);
                asm volatile("ldmatrix.sync.aligned.m8n8.x4.trans.shared.b16 {%0,%1,%2,%3}, [%4];"
                             : "=r"(b[p][0]), "=r"(b[p][1]), "=r"(b[p][2]), "=r"(b[p][3])
                             : "r"(addr));
            }
            // ---- 32 MMAs ----
#pragma unroll
            for (int p = 0; p < 4; p++) {
#pragma unroll
                for (int h = 0; h < 2; h++) {
                    int ni = p * 2 + h;
#pragma unroll
                    for (int mi = 0; mi < 4; mi++) {
                        asm volatile(
                            "mma.sync.aligned.m16n8k16.row.col.f32.bf16.bf16.f32 "
                            "{%0,%1,%2,%3}, {%4,%5,%6,%7}, {%8,%9}, {%0,%1,%2,%3};\n"
                            : "+f"(acc[mi][ni][0]), "+f"(acc[mi][ni][1]),
                              "+f"(acc[mi][ni][2]), "+f"(acc[mi][ni][3])
                            : "r"(a[mi][0]), "r"(a[mi][1]), "r"(a[mi][2]), "r"(a[mi][3]),
                              "r"(b[p][2 * h]), "r"(b[p][2 * h + 1]));
                    }
                }
            }
        }
    }

    // ---------------- epilogue: exact fp32 dequant ----------------
    float inv = 1.0f / (get_scale(0) * get_scale(1));

#pragma unroll
    for (int mi = 0; mi < 4; mi++) {
#pragma unroll
        for (int ni = 0; ni < 8; ni++) {
            int row0 = mBase + wm * 64 + mi * 16 + lg;
            int col  = nBase + wn * 64 + ni * 8 + lt * 2;
            float2 v0, v1;
            v0.x = acc[mi][ni][0] * inv;
            v0.y = acc[mi][ni][1] * inv;
            v1.x = acc[mi][ni][2] * inv;
            v1.y = acc[mi][ni][3] * inv;
            *reinterpret_cast<float2*>(out + (size_t)row0 * NDIM + col) = v0;
            *reinterpret_cast<float2*>(out + (size_t)(row0 + 8) * NDIM + col) = v1;
        }
    }
}

// ---------------- launch ----------------
extern "C" void kernel_launch(void* const* d_in, const int* in_sizes, int n_in,
                              void* d_out, int out_size) {
    const float* lhs = (const float*)d_in[0];
    const float* rhs = (const float*)d_in[1];
    float* out = (float*)d_out;

    cudaFuncSetAttribute(gemm_bf16_kernel,
                         cudaFuncAttributeMaxDynamicSharedMemorySize, GEMM_SMEM);

    init_kernel<<<1, 1>>>();
    amax_kernel<<<2048, 256>>>(lhs, (MDIM * KDIM) / 4, 0);
    amax_kernel<<<2048, 256>>>(rhs, (KDIM * NDIM) / 4, 1);
    quant_kernel<<<(MDIM * KDIM / 16) / 256, 256>>>(lhs, 0);
    quant_kernel<<<(KDIM * NDIM / 16) / 256, 256>>>(rhs, 1);

    dim3 grid(NDIM / 128, MDIM / 256);
    gemm_bf16_kernel<<<grid, 256, GEMM_SMEM>>>(out);
}

// round 7
// speedup vs baseline: 2.3570x; 1.0048x over previous
#include <cuda_runtime.h>
#include <cuda_bf16.h>
#include <cstdint>

#define MDIM 4096
#define NDIM 4096
#define KDIM 4096

// ---------------- device scratch (no allocations allowed) ----------------
__device__ unsigned g_amax[2];                                        // float bits
__device__ __align__(128) unsigned short g_qa[(size_t)MDIM * KDIM];   // lhs quantized ints as bf16, [M][K]
__device__ __align__(128) unsigned short g_qb[(size_t)KDIM * NDIM];   // rhs quantized ints as bf16, [K][N]

// ---------------- calibration ----------------
__global__ void init_kernel() { g_amax[0] = 0u; g_amax[1] = 0u; }

__global__ void amax_kernel(const float* __restrict__ x, int n4, int which) {
    float m = 0.0f;
    int stride = gridDim.x * blockDim.x;
    for (int i = blockIdx.x * blockDim.x + threadIdx.x; i < n4; i += stride) {
        float4 v = reinterpret_cast<const float4*>(x)[i];
        m = fmaxf(m, fmaxf(fmaxf(fabsf(v.x), fabsf(v.y)), fmaxf(fabsf(v.z), fabsf(v.w))));
    }
#pragma unroll
    for (int o = 16; o > 0; o >>= 1)
        m = fmaxf(m, __shfl_xor_sync(0xFFFFFFFFu, m, o));
    if ((threadIdx.x & 31) == 0)
        atomicMax(&g_amax[which], __float_as_uint(m));  // m >= 0: uint order == float order
}

__device__ __forceinline__ float get_scale(int which) {
    float amax = __uint_as_float(g_amax[which]);
    return 127.0f / fmaxf(amax, 1e-12f);
}

// quantize to int on the int8 grid, return EXACT bf16 representation (|v|<=127)
__device__ __forceinline__ unsigned short q8_bf16(float x, float s) {
    float r = rintf(x * s);  // round-half-even, matches jnp.round
    r = fmaxf(-127.0f, fminf(127.0f, r));
    return __bfloat16_as_ushort(__float2bfloat16_rn(r));   // ints <=127 exact in bf16
}

// elementwise quantize: 4 float4 per thread (MLP 4). Destination resolved ON DEVICE.
__global__ void quant_kernel(const float* __restrict__ x, int which) {
    unsigned short* __restrict__ q = which ? g_qb : g_qa;
    float s = get_scale(which);
    int base = (blockIdx.x * blockDim.x + threadIdx.x) * 4;
#pragma unroll
    for (int j = 0; j < 4; j++) {
        int idx = base + j;
        float4 v = reinterpret_cast<const float4*>(x)[idx];
        uint2 o;
        o.x = (uint32_t)q8_bf16(v.x, s) | ((uint32_t)q8_bf16(v.y, s) << 16);
        o.y = (uint32_t)q8_bf16(v.z, s) | ((uint32_t)q8_bf16(v.w, s) << 16);
        reinterpret_cast<uint2*>(q)[idx] = o;
    }
}

// ---------------- bf16 HMMA GEMM ----------------
// CTA tile 256x128 (MxN), K-chunk 64, 4-stage cp.async ring, 8 warps (4Mx2N),
// warp tile 64x64. Register-fragment DOUBLE BUFFERING: LDSMs for k-step s+1 are
// issued before the 32 MMAs of k-step s, hiding LDSM latency behind MMA issue.
#define NSTG 4
#define A_ST_BYTES 32768                 // 256 rows * 128B
#define STAGE_BYTES 49152                // A 32KB + B 16KB
#define GEMM_SMEM (NSTG * STAGE_BYTES)   // 196608
#define NC (KDIM / 64)

__device__ __forceinline__ uint32_t smem_u32(const void* p) {
    uint32_t a;
    asm("{ .reg .u64 t; cvta.to.shared.u64 t, %1; cvt.u32.u64 %0, t; }" : "=r"(a) : "l"(p));
    return a;
}

__global__ void __launch_bounds__(256, 1) gemm_bf16_kernel(float* __restrict__ out) {
    extern __shared__ char sm[];
    const uint32_t sb = smem_u32(sm);

    const int tid  = threadIdx.x;
    const int lane = tid & 31;
    const int warp = tid >> 5;
    const int wm = warp & 3;               // 4 warps along M (64 rows each)
    const int wn = warp >> 2;              // 2 warps along N (64 cols each)
    const int lg = lane >> 2;              // groupID
    const int lt = lane & 3;               // threadID in group

    const int mBase = blockIdx.y * 256;
    const int nBase = blockIdx.x * 128;

    float acc[4][8][4];
#pragma unroll
    for (int mi = 0; mi < 4; mi++)
#pragma unroll
        for (int ni = 0; ni < 8; ni++)
#pragma unroll
            for (int r = 0; r < 4; r++) acc[mi][ni][r] = 0.0f;

    // precomputed ldmatrix lane addressing
    const int a_row_in = lane & 15;        // row within 16-row fragment
    const int a_hi = lane >> 4;            // chunk select
    // ---- cp.async issue for chunk ch into stage ch%4 ----
    auto issue = [&](int ch) {
        if (ch < NC) {
            const int kt = ch * 64;
            const uint32_t st = sb + (ch % NSTG) * STAGE_BYTES;
#pragma unroll
            for (int it = 0; it < 8; it++) {
                int c = tid + it * 256;
                int row = c >> 3, cb = c & 7;
                uint32_t dst = st + row * 128 + ((cb ^ (row & 7)) << 4);
                const void* src = g_qa + (size_t)(mBase + row) * KDIM + kt + cb * 8;
                asm volatile("cp.async.cg.shared.global [%0], [%1], 16;"
                             :: "r"(dst), "l"(src) : "memory");
            }
#pragma unroll
            for (int it = 0; it < 4; it++) {
                int c = tid + it * 256;
                int row = c >> 4, cb = c & 15;
                uint32_t dst = st + A_ST_BYTES + row * 256 + ((cb ^ (row & 7)) << 4);
                const void* src = g_qb + (size_t)(kt + row) * NDIM + nBase + cb * 8;
                asm volatile("cp.async.cg.shared.global [%0], [%1], 16;"
                             :: "r"(dst), "l"(src) : "memory");
            }
        }
        asm volatile("cp.async.commit_group;" ::: "memory");
    };

    // fragment loaders (ks = k-step 0..3 within chunk)
    auto ldA = [&](uint32_t stA, int ks, uint32_t a[4][4]) {
#pragma unroll
        for (int mi = 0; mi < 4; mi++) {
            int row = wm * 64 + mi * 16 + a_row_in;
            int cb  = ks * 2 + a_hi;
            uint32_t addr = stA + row * 128 + ((cb ^ (row & 7)) << 4);
            asm volatile("ldmatrix.sync.aligned.m8n8.x4.shared.b16 {%0,%1,%2,%3}, [%4];"
                         : "=r"(a[mi][0]), "=r"(a[mi][1]), "=r"(a[mi][2]), "=r"(a[mi][3])
                         : "r"(addr));
        }
    };
    auto ldB = [&](uint32_t stB, int ks, uint32_t b[4][4]) {
#pragma unroll
        for (int p = 0; p < 4; p++) {
            int krow = ks * 16 + a_row_in;
            int cb   = (wn * 8 + p * 2) + a_hi;
            uint32_t addr = stB + krow * 256 + ((cb ^ (krow & 7)) << 4);
            asm volatile("ldmatrix.sync.aligned.m8n8.x4.trans.shared.b16 {%0,%1,%2,%3}, [%4];"
                         : "=r"(b[p][0]), "=r"(b[p][1]), "=r"(b[p][2]), "=r"(b[p][3])
                         : "r"(addr));
        }
    };

    issue(0); issue(1); issue(2);

    uint32_t afrag[2][4][4], bfrag[2][4][4];

    for (int ch = 0; ch < NC; ch++) {
        asm volatile("cp.async.wait_group 2;" ::: "memory");   // chunk ch resident
        __syncthreads();                                       // visible; stage ch-1 free
        issue(ch + 3);                                         // refill stage (ch-1)%4

        const uint32_t stA = sb + (ch % NSTG) * STAGE_BYTES;
        const uint32_t stB = stA + A_ST_BYTES;

        // prologue: fragments for k-step 0
        ldA(stA, 0, afrag[0]);
        ldB(stB, 0, bfrag[0]);

#pragma unroll
        for (int ks = 0; ks < 4; ks++) {
            const int cur = ks & 1, nxt = cur ^ 1;
            if (ks < 3) {                                      // prefetch next k-step
                ldA(stA, ks + 1, afrag[nxt]);
                ldB(stB, ks + 1, bfrag[nxt]);
            }
            // ---- 32 MMAs on current fragments ----
#pragma unroll
            for (int p = 0; p < 4; p++) {
#pragma unroll
                for (int h = 0; h < 2; h++) {
                    int ni = p * 2 + h;
#pragma unroll
                    for (int mi = 0; mi < 4; mi++) {
                        asm volatile(
                            "mma.sync.aligned.m16n8k16.row.col.f32.bf16.bf16.f32 "
                            "{%0,%1,%2,%3}, {%4,%5,%6,%7}, {%8,%9}, {%0,%1,%2,%3};\n"
                            : "+f"(acc[mi][ni][0]), "+f"(acc[mi][ni][1]),
                              "+f"(acc[mi][ni][2]), "+f"(acc[mi][ni][3])
                            : "r"(afrag[cur][mi][0]), "r"(afrag[cur][mi][1]),
                              "r"(afrag[cur][mi][2]), "r"(afrag[cur][mi][3]),
                              "r"(bfrag[cur][p][2 * h]), "r"(bfrag[cur][p][2 * h + 1]));
                    }
                }
            }
        }
    }

    // ---------------- epilogue: exact fp32 dequant ----------------
    float inv = 1.0f / (get_scale(0) * get_scale(1));

#pragma unroll
    for (int mi = 0; mi < 4; mi++) {
#pragma unroll
        for (int ni = 0; ni < 8; ni++) {
            int row0 = mBase + wm * 64 + mi * 16 + lg;
            int col  = nBase + wn * 64 + ni * 8 + lt * 2;
            float2 v0, v1;
            v0.x = acc[mi][ni][0] * inv;
            v0.y = acc[mi][ni][1] * inv;
            v1.x = acc[mi][ni][2] * inv;
            v1.y = acc[mi][ni][3] * inv;
            *reinterpret_cast<float2*>(out + (size_t)row0 * NDIM + col) = v0;
            *reinterpret_cast<float2*>(out + (size_t)(row0 + 8) * NDIM + col) = v1;
        }
    }
}

// ---------------- launch ----------------
extern "C" void kernel_launch(void* const* d_in, const int* in_sizes, int n_in,
                              void* d_out, int out_size) {
    const float* lhs = (const float*)d_in[0];
    const float* rhs = (const float*)d_in[1];
    float* out = (float*)d_out;

    cudaFuncSetAttribute(gemm_bf16_kernel,
                         cudaFuncAttributeMaxDynamicSharedMemorySize, GEMM_SMEM);

    init_kernel<<<1, 1>>>();
    amax_kernel<<<2048, 256>>>(lhs, (MDIM * KDIM) / 4, 0);
    amax_kernel<<<2048, 256>>>(rhs, (KDIM * NDIM) / 4, 1);
    quant_kernel<<<(MDIM * KDIM / 16) / 256, 256>>>(lhs, 0);
    quant_kernel<<<(KDIM * NDIM / 16) / 256, 256>>>(rhs, 1);

    dim3 grid(NDIM / 128, MDIM / 256);
    gemm_bf16_kernel<<<grid, 256, GEMM_SMEM>>>(out);
}

// round 8
// speedup vs baseline: 2.4481x; 1.0386x over previous
#include <cuda_runtime.h>
#include <cuda_bf16.h>
#include <cstdint>

#define MDIM 4096
#define NDIM 4096
#define KDIM 4096

// ---------------- device scratch (no allocations allowed) ----------------
__device__ unsigned g_amax[2];                                        // float bits
__device__ __align__(128) unsigned short g_qa[(size_t)MDIM * KDIM];   // lhs quantized ints as bf16, [M][K]
__device__ __align__(128) unsigned short g_qb[(size_t)KDIM * NDIM];   // rhs quantized ints as bf16, [K][N]

// ---------------- calibration ----------------
// One launch covers BOTH tensors: blocks [0, half) -> lhs, [half, 2*half) -> rhs.
__global__ void amax2_kernel(const float* __restrict__ lhs,
                             const float* __restrict__ rhs, int n4each) {
    const int half = gridDim.x >> 1;
    const int which = blockIdx.x >= half;
    const float* __restrict__ x = which ? rhs : lhs;
    const int bid = blockIdx.x - which * half;

    float m = 0.0f;
    const int stride = half * blockDim.x;
    for (int i = bid * blockDim.x + threadIdx.x; i < n4each; i += stride) {
        float4 v = reinterpret_cast<const float4*>(x)[i];
        m = fmaxf(m, fmaxf(fmaxf(fabsf(v.x), fabsf(v.y)), fmaxf(fabsf(v.z), fabsf(v.w))));
    }
#pragma unroll
    for (int o = 16; o > 0; o >>= 1)
        m = fmaxf(m, __shfl_xor_sync(0xFFFFFFFFu, m, o));
    if ((threadIdx.x & 31) == 0)
        atomicMax(&g_amax[which], __float_as_uint(m));  // m >= 0: uint order == float order
}

__device__ __forceinline__ float get_scale(int which) {
    float amax = __uint_as_float(g_amax[which]);
    return 127.0f / fmaxf(amax, 1e-12f);
}

// quantize to int on the int8 grid, return EXACT bf16 representation (|v|<=127)
__device__ __forceinline__ unsigned short q8_bf16(float x, float s) {
    float r = rintf(x * s);  // round-half-even, matches jnp.round
    r = fmaxf(-127.0f, fminf(127.0f, r));
    return __bfloat16_as_ushort(__float2bfloat16_rn(r));   // ints <=127 exact in bf16
}

// One launch quantizes BOTH tensors; 4 float4 per thread (MLP 4).
__global__ void quant2_kernel(const float* __restrict__ lhs,
                              const float* __restrict__ rhs) {
    const int half = gridDim.x >> 1;
    const int which = blockIdx.x >= half;
    const float* __restrict__ x = which ? rhs : lhs;
    unsigned short* __restrict__ q = which ? g_qb : g_qa;
    const int bid = blockIdx.x - which * half;

    float s = get_scale(which);
    int base = (bid * blockDim.x + threadIdx.x) * 4;
#pragma unroll
    for (int j = 0; j < 4; j++) {
        int idx = base + j;
        float4 v = reinterpret_cast<const float4*>(x)[idx];
        uint2 o;
        o.x = (uint32_t)q8_bf16(v.x, s) | ((uint32_t)q8_bf16(v.y, s) << 16);
        o.y = (uint32_t)q8_bf16(v.z, s) | ((uint32_t)q8_bf16(v.w, s) << 16);
        reinterpret_cast<uint2*>(q)[idx] = o;
    }
}

// ---------------- bf16 HMMA GEMM (unchanged from round 7 best) ----------------
// CTA tile 256x128 (MxN), K-chunk 64, 4-stage cp.async ring, 8 warps (4Mx2N),
// warp tile 64x64, register-fragment double buffering.
#define NSTG 4
#define A_ST_BYTES 32768                 // 256 rows * 128B
#define STAGE_BYTES 49152                // A 32KB + B 16KB
#define GEMM_SMEM (NSTG * STAGE_BYTES)   // 196608
#define NC (KDIM / 64)

__device__ __forceinline__ uint32_t smem_u32(const void* p) {
    uint32_t a;
    asm("{ .reg .u64 t; cvta.to.shared.u64 t, %1; cvt.u32.u64 %0, t; }" : "=r"(a) : "l"(p));
    return a;
}

__global__ void __launch_bounds__(256, 1) gemm_bf16_kernel(float* __restrict__ out) {
    extern __shared__ char sm[];
    const uint32_t sb = smem_u32(sm);

    const int tid  = threadIdx.x;
    const int lane = tid & 31;
    const int warp = tid >> 5;
    const int wm = warp & 3;               // 4 warps along M (64 rows each)
    const int wn = warp >> 2;              // 2 warps along N (64 cols each)
    const int lg = lane >> 2;              // groupID
    const int lt = lane & 3;               // threadID in group

    const int mBase = blockIdx.y * 256;
    const int nBase = blockIdx.x * 128;

    float acc[4][8][4];
#pragma unroll
    for (int mi = 0; mi < 4; mi++)
#pragma unroll
        for (int ni = 0; ni < 8; ni++)
#pragma unroll
            for (int r = 0; r < 4; r++) acc[mi][ni][r] = 0.0f;

    const int a_row_in = lane & 15;
    const int a_hi = lane >> 4;

    auto issue = [&](int ch) {
        if (ch < NC) {
            const int kt = ch * 64;
            const uint32_t st = sb + (ch % NSTG) * STAGE_BYTES;
#pragma unroll
            for (int it = 0; it < 8; it++) {
                int c = tid + it * 256;
                int row = c >> 3, cb = c & 7;
                uint32_t dst = st + row * 128 + ((cb ^ (row & 7)) << 4);
                const void* src = g_qa + (size_t)(mBase + row) * KDIM + kt + cb * 8;
                asm volatile("cp.async.cg.shared.global [%0], [%1], 16;"
                             :: "r"(dst), "l"(src) : "memory");
            }
#pragma unroll
            for (int it = 0; it < 4; it++) {
                int c = tid + it * 256;
                int row = c >> 4, cb = c & 15;
                uint32_t dst = st + A_ST_BYTES + row * 256 + ((cb ^ (row & 7)) << 4);
                const void* src = g_qb + (size_t)(kt + row) * NDIM + nBase + cb * 8;
                asm volatile("cp.async.cg.shared.global [%0], [%1], 16;"
                             :: "r"(dst), "l"(src) : "memory");
            }
        }
        asm volatile("cp.async.commit_group;" ::: "memory");
    };

    auto ldA = [&](uint32_t stA, int ks, uint32_t a[4][4]) {
#pragma unroll
        for (int mi = 0; mi < 4; mi++) {
            int row = wm * 64 + mi * 16 + a_row_in;
            int cb  = ks * 2 + a_hi;
            uint32_t addr = stA + row * 128 + ((cb ^ (row & 7)) << 4);
            asm volatile("ldmatrix.sync.aligned.m8n8.x4.shared.b16 {%0,%1,%2,%3}, [%4];"
                         : "=r"(a[mi][0]), "=r"(a[mi][1]), "=r"(a[mi][2]), "=r"(a[mi][3])
                         : "r"(addr));
        }
    };
    auto ldB = [&](uint32_t stB, int ks, uint32_t b[4][4]) {
#pragma unroll
        for (int p = 0; p < 4; p++) {
            int krow = ks * 16 + a_row_in;
            int cb   = (wn * 8 + p * 2) + a_hi;
            uint32_t addr = stB + krow * 256 + ((cb ^ (krow & 7)) << 4);
            asm volatile("ldmatrix.sync.aligned.m8n8.x4.trans.shared.b16 {%0,%1,%2,%3}, [%4];"
                         : "=r"(b[p][0]), "=r"(b[p][1]), "=r"(b[p][2]), "=r"(b[p][3])
                         : "r"(addr));
        }
    };

    issue(0); issue(1); issue(2);

    uint32_t afrag[2][4][4], bfrag[2][4][4];

    for (int ch = 0; ch < NC; ch++) {
        asm volatile("cp.async.wait_group 2;" ::: "memory");
        __syncthreads();
        issue(ch + 3);

        const uint32_t stA = sb + (ch % NSTG) * STAGE_BYTES;
        const uint32_t stB = stA + A_ST_BYTES;

        ldA(stA, 0, afrag[0]);
        ldB(stB, 0, bfrag[0]);

#pragma unroll
        for (int ks = 0; ks < 4; ks++) {
            const int cur = ks & 1, nxt = cur ^ 1;
            if (ks < 3) {
                ldA(stA, ks + 1, afrag[nxt]);
                ldB(stB, ks + 1, bfrag[nxt]);
            }
#pragma unroll
            for (int p = 0; p < 4; p++) {
#pragma unroll
                for (int h = 0; h < 2; h++) {
                    int ni = p * 2 + h;
#pragma unroll
                    for (int mi = 0; mi < 4; mi++) {
                        asm volatile(
                            "mma.sync.aligned.m16n8k16.row.col.f32.bf16.bf16.f32 "
                            "{%0,%1,%2,%3}, {%4,%5,%6,%7}, {%8,%9}, {%0,%1,%2,%3};\n"
                            : "+f"(acc[mi][ni][0]), "+f"(acc[mi][ni][1]),
                              "+f"(acc[mi][ni][2]), "+f"(acc[mi][ni][3])
                            : "r"(afrag[cur][mi][0]), "r"(afrag[cur][mi][1]),
                              "r"(afrag[cur][mi][2]), "r"(afrag[cur][mi][3]),
                              "r"(bfrag[cur][p][2 * h]), "r"(bfrag[cur][p][2 * h + 1]));
                    }
                }
            }
        }
    }

    // ---------------- epilogue: exact fp32 dequant ----------------
    float inv = 1.0f / (get_scale(0) * get_scale(1));

#pragma unroll
    for (int mi = 0; mi < 4; mi++) {
#pragma unroll
        for (int ni = 0; ni < 8; ni++) {
            int row0 = mBase + wm * 64 + mi * 16 + lg;
            int col  = nBase + wn * 64 + ni * 8 + lt * 2;
            float2 v0, v1;
            v0.x = acc[mi][ni][0] * inv;
            v0.y = acc[mi][ni][1] * inv;
            v1.x = acc[mi][ni][2] * inv;
            v1.y = acc[mi][ni][3] * inv;
            *reinterpret_cast<float2*>(out + (size_t)row0 * NDIM + col) = v0;
            *reinterpret_cast<float2*>(out + (size_t)(row0 + 8) * NDIM + col) = v1;
        }
    }
}

// ---------------- launch ----------------
extern "C" void kernel_launch(void* const* d_in, const int* in_sizes, int n_in,
                              void* d_out, int out_size) {
    const float* lhs = (const float*)d_in[0];
    const float* rhs = (const float*)d_in[1];
    float* out = (float*)d_out;

    cudaFuncSetAttribute(gemm_bf16_kernel,
                         cudaFuncAttributeMaxDynamicSharedMemorySize, GEMM_SMEM);

    // reset amax accumulators (graph-capturable memset node; no kernel launch)
    void* amax_ptr = nullptr;
    cudaGetSymbolAddress(&amax_ptr, g_amax);
    cudaMemsetAsync(amax_ptr, 0, 2 * sizeof(unsigned));

    // fused abs-max over both tensors (1024 blocks per tensor)
    amax2_kernel<<<2048, 256>>>(lhs, rhs, (MDIM * KDIM) / 4);

    // fused quantization of both tensors (4096 blocks per tensor)
    quant2_kernel<<<8192, 256>>>(lhs, rhs);

    dim3 grid(NDIM / 128, MDIM / 256);
    gemm_bf16_kernel<<<grid, 256, GEMM_SMEM>>>(out);
}